// round 14
// baseline (speedup 1.0000x reference)
#include <cuda_runtime.h>
#include <cuda_fp16.h>

#define N_NODES 100000
#define E_EDGES 1600000
#define D 128
#define BN_EPS 1e-5f
#define MAX_N 131072
#define BUCKET 64          // padded CSR capacity per node; P(deg>=64)~1e-18

// Scratch (static device globals — allocation-free, zero-initialized at load).
__device__ __half g_yh[(size_t)N_NODES * D];   // 25.6 MB: y = x @ W (fp16)
__device__ __half g_zh[(size_t)N_NODES * D];   // 25.6 MB: z = A @ y (fp16)
__device__ int    g_cnt[MAX_N];                // per-dst cursor; ALWAYS zero at
                                               // call entry (reset by gather)
__device__ int2   g_csr[(size_t)MAX_N * BUCKET];  // 67 MB padded buckets
__device__ float  g_stats[2 * D];              // zeroed by scatter each call

// ---------------- bit-reinterpret helpers ----------------
__device__ __forceinline__ unsigned int h2_as_u32(__half2 h) {
    return *reinterpret_cast<unsigned int*>(&h);
}
__device__ __forceinline__ __half2 u32_as_h2(unsigned int u) {
    return *reinterpret_cast<__half2*>(&u);
}

// ---------------- f32x2 packed-FMA helpers ----------------
__device__ __forceinline__ unsigned long long pack2(float lo, float hi) {
    unsigned long long r;
    asm("mov.b64 %0, {%1, %2};" : "=l"(r) : "f"(lo), "f"(hi));
    return r;
}
__device__ __forceinline__ void unpack2(unsigned long long v, float& lo, float& hi) {
    asm("mov.b64 {%0, %1}, %2;" : "=f"(lo), "=f"(hi) : "l"(v));
}
__device__ __forceinline__ void ffma2(unsigned long long& d,
                                      unsigned long long a,
                                      unsigned long long b) {
    asm("fma.rn.f32x2 %0, %1, %2, %0;" : "+l"(d) : "l"(a), "l"(b));
}

// ---------------------------------------------------------------------------
// K1: scatter edges into padded buckets (4 edges per thread, int4 loads).
// Block 0 also zeros g_stats (consumed later by gather/norm this call).
// ---------------------------------------------------------------------------
__device__ __forceinline__ void scat1(int d, int s, float v, int n_rows) {
    if ((unsigned)d < (unsigned)n_rows) {
        int slot = atomicAdd(&g_cnt[d], 1);
        if (slot < BUCKET) {
            int ss = ((unsigned)s < (unsigned)n_rows) ? s : 0;
            g_csr[((size_t)d << 6) + slot] = make_int2(ss, __float_as_int(v));
        }
    }
}

__global__ void k_scatter(const int4* __restrict__ esrc4,
                          const int4* __restrict__ edst4,
                          const float4* __restrict__ eval4,
                          int n_e4, int n_rows) {
    if (blockIdx.x == 0 && threadIdx.x < 2 * D) g_stats[threadIdx.x] = 0.f;
    int i = blockIdx.x * blockDim.x + threadIdx.x;
    if (i >= n_e4) return;
    int4 d = edst4[i];
    int4 s = esrc4[i];
    float4 v = eval4[i];
    scat1(d.x, s.x, v.x, n_rows);
    scat1(d.y, s.y, v.y, n_rows);
    scat1(d.z, s.z, v.z, n_rows);
    scat1(d.w, s.w, v.w, n_rows);
}

// ---------------------------------------------------------------------------
// K2: tensor-core GEMM y = x @ W (fp16 in, fp32 accum, fp16 out).
// Block: 128x128 tile, 8 warps as 4(m) x 2(n), warp tile 32x64.
// ---------------------------------------------------------------------------
#define SROW 136
#define GEMM_SMEM (2 * 128 * SROW * sizeof(__half))   // 69632 B

__global__ __launch_bounds__(256) void k_gemm_xw(const float* __restrict__ X,
                                                 const float* __restrict__ W,
                                                 int n_rows) {
    extern __shared__ __half smh[];
    __half* sA = smh;                 // [128][SROW]
    __half* sB = smh + 128 * SROW;    // [128][SROW]

    int tid = threadIdx.x;
    int wid = tid >> 5;
    int lane = tid & 31;
    int gr = lane >> 2;
    int tc = (lane & 3) * 2;

    int mbase = (wid & 3) * 32;
    int nbase = (wid >> 2) * 64;

#pragma unroll
    for (int q = 0; q < 16; q++) {
        int f = tid + 256 * q;
        int r = f >> 5;
        int kq = f & 31;
        int grow = blockIdx.x * 128 + r;
        float4 v = make_float4(0.f, 0.f, 0.f, 0.f);
        if (grow < n_rows)
            v = *reinterpret_cast<const float4*>(&X[(size_t)grow * D + kq * 4]);
        __half2 h0 = __floats2half2_rn(v.x, v.y);
        __half2 h1 = __floats2half2_rn(v.z, v.w);
        uint2 pk;
        pk.x = h2_as_u32(h0);
        pk.y = h2_as_u32(h1);
        *reinterpret_cast<uint2*>(&sA[r * SROW + kq * 4]) = pk;

        float4 w = *reinterpret_cast<const float4*>(&W[(size_t)r * D + kq * 4]);
        __half2 g0 = __floats2half2_rn(w.x, w.y);
        __half2 g1 = __floats2half2_rn(w.z, w.w);
        uint2 pw;
        pw.x = h2_as_u32(g0);
        pw.y = h2_as_u32(g1);
        *reinterpret_cast<uint2*>(&sB[r * SROW + kq * 4]) = pw;
    }
    __syncthreads();

    float c[2][8][4];
#pragma unroll
    for (int mt = 0; mt < 2; mt++)
#pragma unroll
        for (int nt = 0; nt < 8; nt++)
#pragma unroll
            for (int j = 0; j < 4; j++) c[mt][nt][j] = 0.f;

    const unsigned short* sBu = reinterpret_cast<const unsigned short*>(sB);

#pragma unroll
    for (int ks = 0; ks < 8; ks++) {
        int kb = ks * 16;
        unsigned int a[2][4];
#pragma unroll
        for (int mt = 0; mt < 2; mt++) {
            int r0 = mbase + mt * 16 + gr;
            a[mt][0] = *reinterpret_cast<const unsigned int*>(&sA[r0 * SROW + kb + tc]);
            a[mt][1] = *reinterpret_cast<const unsigned int*>(&sA[(r0 + 8) * SROW + kb + tc]);
            a[mt][2] = *reinterpret_cast<const unsigned int*>(&sA[r0 * SROW + kb + 8 + tc]);
            a[mt][3] = *reinterpret_cast<const unsigned int*>(&sA[(r0 + 8) * SROW + kb + 8 + tc]);
        }
#pragma unroll
        for (int nt = 0; nt < 8; nt++) {
            int nb = nbase + nt * 8 + gr;
            unsigned int b0 = (unsigned int)sBu[(kb + tc) * SROW + nb] |
                              ((unsigned int)sBu[(kb + tc + 1) * SROW + nb] << 16);
            unsigned int b1 = (unsigned int)sBu[(kb + 8 + tc) * SROW + nb] |
                              ((unsigned int)sBu[(kb + 8 + tc + 1) * SROW + nb] << 16);
#pragma unroll
            for (int mt = 0; mt < 2; mt++) {
                asm volatile(
                    "mma.sync.aligned.m16n8k16.row.col.f32.f16.f16.f32 "
                    "{%0,%1,%2,%3}, {%4,%5,%6,%7}, {%8,%9}, {%0,%1,%2,%3};\n"
                    : "+f"(c[mt][nt][0]), "+f"(c[mt][nt][1]),
                      "+f"(c[mt][nt][2]), "+f"(c[mt][nt][3])
                    : "r"(a[mt][0]), "r"(a[mt][1]), "r"(a[mt][2]), "r"(a[mt][3]),
                      "r"(b0), "r"(b1));
            }
        }
    }

    __half* Y = g_yh;
#pragma unroll
    for (int mt = 0; mt < 2; mt++) {
        int r0 = blockIdx.x * 128 + mbase + mt * 16 + gr;
#pragma unroll
        for (int nt = 0; nt < 8; nt++) {
            int cb = nbase + nt * 8 + tc;
            if (r0 < n_rows) {
                __half2 lo = __floats2half2_rn(c[mt][nt][0], c[mt][nt][1]);
                *reinterpret_cast<unsigned int*>(&Y[(size_t)r0 * D + cb]) = h2_as_u32(lo);
            }
            if (r0 + 8 < n_rows) {
                __half2 hi = __floats2half2_rn(c[mt][nt][2], c[mt][nt][3]);
                *reinterpret_cast<unsigned int*>(&Y[(size_t)(r0 + 8) * D + cb]) = h2_as_u32(hi);
            }
        }
    }
}

// ---------------------------------------------------------------------------
// K3: gather-reduce over fp16 y -> fp16 z rows, fused BN stats.
// Grid-stride warp-per-node; lane owns 4 columns. 6-edge unroll, int4 bucket
// loads, f32x2 packed-FMA accumulation (2 FFMA2/edge). Resets g_cnt after use.
// ---------------------------------------------------------------------------
__device__ __forceinline__ void acc_edge2(unsigned long long& a01,
                                          unsigned long long& a23,
                                          uint2 r, float v) {
    float2 f0 = __half22float2(u32_as_h2(r.x));
    float2 f1 = __half22float2(u32_as_h2(r.y));
    unsigned long long vv = pack2(v, v);
    ffma2(a01, pack2(f0.x, f0.y), vv);
    ffma2(a23, pack2(f1.x, f1.y), vv);
}

__global__ __launch_bounds__(256, 7) void k_gather(int n_rows, int total_warps) {
    __shared__ float s_sum[D];
    __shared__ float s_sq[D];
    if (threadIdx.x < D) { s_sum[threadIdx.x] = 0.f; s_sq[threadIdx.x] = 0.f; }
    __syncthreads();

    int gwarp = (blockIdx.x * blockDim.x + threadIdx.x) >> 5;
    int lane = threadIdx.x & 31;
    const uint2* y2 = reinterpret_cast<const uint2*>(g_yh);
    uint2* z2 = reinterpret_cast<uint2*>(g_zh);

    float4 csum = make_float4(0.f, 0.f, 0.f, 0.f);
    float4 csq = make_float4(0.f, 0.f, 0.f, 0.f);

    for (int node = gwarp; node < n_rows; node += total_warps) {
        const int4* bucket4 = reinterpret_cast<const int4*>(&g_csr[(size_t)node << 6]);
        int deg = g_cnt[node];
        if (lane == 0) g_cnt[node] = 0;   // restore all-zero invariant
        if (deg > BUCKET) deg = BUCKET;

        unsigned long long a01 = 0ULL, a23 = 0ULL;
        int p = 0;
        for (; p + 5 < deg; p += 6) {          // 6 edges = 3 int4 loads
            int4 e4[3];
#pragma unroll
            for (int q = 0; q < 3; q++) e4[q] = bucket4[(p >> 1) + q];
            uint2 r[6];
#pragma unroll
            for (int q = 0; q < 3; q++) {
                r[2 * q]     = y2[(size_t)e4[q].x * 32 + lane];
                r[2 * q + 1] = y2[(size_t)e4[q].z * 32 + lane];
            }
#pragma unroll
            for (int q = 0; q < 3; q++) {
                acc_edge2(a01, a23, r[2 * q],     __int_as_float(e4[q].y));
                acc_edge2(a01, a23, r[2 * q + 1], __int_as_float(e4[q].w));
            }
        }
        for (; p + 1 < deg; p += 2) {
            int4 e = bucket4[p >> 1];
            uint2 r0 = y2[(size_t)e.x * 32 + lane];
            uint2 r1 = y2[(size_t)e.z * 32 + lane];
            acc_edge2(a01, a23, r0, __int_as_float(e.y));
            acc_edge2(a01, a23, r1, __int_as_float(e.w));
        }
        if (p < deg) {
            int2 e0 = g_csr[((size_t)node << 6) + p];
            uint2 ra = y2[(size_t)e0.x * 32 + lane];
            acc_edge2(a01, a23, ra, __int_as_float(e0.y));
        }

        float4 acc;
        unpack2(a01, acc.x, acc.y);
        unpack2(a23, acc.z, acc.w);

        __half2 z01 = __floats2half2_rn(acc.x, acc.y);
        __half2 z23 = __floats2half2_rn(acc.z, acc.w);
        uint2 zo;
        zo.x = h2_as_u32(z01);
        zo.y = h2_as_u32(z23);
        z2[(size_t)node * 32 + lane] = zo;

        float2 f01 = __half22float2(z01);
        float2 f23 = __half22float2(z23);
        csum.x += f01.x; csum.y += f01.y; csum.z += f23.x; csum.w += f23.y;
        csq.x += f01.x * f01.x; csq.y += f01.y * f01.y;
        csq.z += f23.x * f23.x; csq.w += f23.y * f23.y;
    }

    int c0 = lane * 4;
    atomicAdd(&s_sum[c0 + 0], csum.x);
    atomicAdd(&s_sum[c0 + 1], csum.y);
    atomicAdd(&s_sum[c0 + 2], csum.z);
    atomicAdd(&s_sum[c0 + 3], csum.w);
    atomicAdd(&s_sq[c0 + 0], csq.x);
    atomicAdd(&s_sq[c0 + 1], csq.y);
    atomicAdd(&s_sq[c0 + 2], csq.z);
    atomicAdd(&s_sq[c0 + 3], csq.w);
    __syncthreads();
    if (threadIdx.x < D) {
        atomicAdd(&g_stats[threadIdx.x], s_sum[threadIdx.x]);
        atomicAdd(&g_stats[D + threadIdx.x], s_sq[threadIdx.x]);
    }
}

// ---------------------------------------------------------------------------
// K4: normalize fp16 z -> fp32 out. Bias cancels in BN.
// ---------------------------------------------------------------------------
__global__ __launch_bounds__(256) void k_norm(float4* __restrict__ out,
                                              const float* __restrict__ gamma,
                                              const float* __restrict__ beta,
                                              float inv_n, int n_rows) {
    __shared__ float s_scale[D];
    __shared__ float s_shift[D];
    if (threadIdx.x < D) {
        int c = threadIdx.x;
        float mean = g_stats[c] * inv_n;
        float var = g_stats[D + c] * inv_n - mean * mean;
        float inv = rsqrtf(var + BN_EPS);
        float sc = gamma[c] * inv;
        s_scale[c] = sc;
        s_shift[c] = beta[c] - mean * sc;
    }
    __syncthreads();

    const uint2* z2 = reinterpret_cast<const uint2*>(g_zh);
    size_t total = (size_t)n_rows * (D / 4);
    size_t stride = (size_t)gridDim.x * blockDim.x;
    for (size_t i = (size_t)blockIdx.x * blockDim.x + threadIdx.x; i < total;
         i += stride) {
        int c4 = (int)(i & 31);
        uint2 zr = z2[i];
        float2 f01 = __half22float2(u32_as_h2(zr.x));
        float2 f23 = __half22float2(u32_as_h2(zr.y));
        float4 sc = reinterpret_cast<const float4*>(s_scale)[c4];
        float4 sh = reinterpret_cast<const float4*>(s_shift)[c4];
        float4 v;
        v.x = f01.x * sc.x + sh.x;
        v.y = f01.y * sc.y + sh.y;
        v.z = f23.x * sc.z + sh.z;
        v.w = f23.y * sc.w + sh.w;
        out[i] = v;
    }
}

// ---------------------------------------------------------------------------
extern "C" void kernel_launch(void* const* d_in, const int* in_sizes, int n_in,
                              void* d_out, int out_size) {
    const float* x    = (const float*)d_in[0];
    const int*   esrc = (const int*)d_in[1];
    const int*   edst = (const int*)d_in[2];
    const float* eval = (const float*)d_in[3];
    const float* W    = (const float*)d_in[4];
    // d_in[5] = bias: cancels analytically in BatchNorm — unused.
    const float* gamm = (const float*)d_in[6];
    const float* beta = (const float*)d_in[7];
    float* out = (float*)d_out;

    int n_rows = in_sizes[0] / D;      // 100000
    int n_edges = in_sizes[1];         // 1600000

    static cudaStream_t s2 = nullptr;
    static cudaEvent_t ev_fork = nullptr, ev_join = nullptr;
    if (s2 == nullptr) {
        cudaFuncSetAttribute(k_gemm_xw, cudaFuncAttributeMaxDynamicSharedMemorySize,
                             (int)GEMM_SMEM);
        cudaStreamCreateWithFlags(&s2, cudaStreamNonBlocking);
        cudaEventCreateWithFlags(&ev_fork, cudaEventDisableTiming);
        cudaEventCreateWithFlags(&ev_join, cudaEventDisableTiming);
    }

    // Fork: tensor-core GEMM on s2, concurrent with bucket-CSR scatter.
    cudaEventRecord(ev_fork, 0);
    cudaStreamWaitEvent(s2, ev_fork, 0);
    k_gemm_xw<<<(n_rows + 127) / 128, 256, GEMM_SMEM, s2>>>(x, W, n_rows);
    cudaEventRecord(ev_join, s2);

    // Bucket scatter on default stream. g_cnt is all-zero at entry
    // (static init on call 1; gather resets it every call). Block 0 zeros stats.
    k_scatter<<<(n_edges / 4 + 255) / 256, 256>>>((const int4*)esrc,
                                                  (const int4*)edst,
                                                  (const float4*)eval,
                                                  n_edges / 4, n_rows);

    // Join: gather needs both y and CSR.
    cudaStreamWaitEvent(0, ev_join, 0);

    {
        int blocks = 1036;               // 7 blocks/SM, one wave
        int total_warps = blocks * (256 / 32);
        k_gather<<<blocks, 256>>>(n_rows, total_warps);
    }
    k_norm<<<1776, 256>>>((float4*)out, gamm, beta, 1.0f / (float)n_rows, n_rows);
}

// round 15
// speedup vs baseline: 1.0234x; 1.0234x over previous
#include <cuda_runtime.h>
#include <cuda_fp16.h>

#define N_NODES 100000
#define E_EDGES 1600000
#define D 128
#define BN_EPS 1e-5f
#define MAX_N 131072
#define BUCKET 64          // padded CSR capacity per node; P(deg>=64)~1e-18

// Scratch (static device globals — allocation-free, zero-initialized at load).
__device__ __half g_yh[(size_t)N_NODES * D];   // 25.6 MB: y = x @ W (fp16)
__device__ __half g_zh[(size_t)N_NODES * D];   // 25.6 MB: z = A @ y (fp16)
__device__ int    g_cnt[MAX_N];                // per-dst cursor; ALWAYS zero at
                                               // call entry (reset by gather)
__device__ int2   g_csr[(size_t)MAX_N * BUCKET];  // 67 MB padded buckets
__device__ float  g_stats[2 * D];              // zeroed by scatter each call

// ---------------- bit-reinterpret helpers ----------------
__device__ __forceinline__ unsigned int h2_as_u32(__half2 h) {
    return *reinterpret_cast<unsigned int*>(&h);
}
__device__ __forceinline__ __half2 u32_as_h2(unsigned int u) {
    return *reinterpret_cast<__half2*>(&u);
}

// ---------------------------------------------------------------------------
// K1: scatter edges into padded buckets (4 edges per thread, int4 loads).
// Block 0 also zeros g_stats (consumed later by gather/norm this call).
// ---------------------------------------------------------------------------
__device__ __forceinline__ void scat1(int d, int s, float v, int n_rows) {
    if ((unsigned)d < (unsigned)n_rows) {
        int slot = atomicAdd(&g_cnt[d], 1);
        if (slot < BUCKET) {
            int ss = ((unsigned)s < (unsigned)n_rows) ? s : 0;
            g_csr[((size_t)d << 6) + slot] = make_int2(ss, __float_as_int(v));
        }
    }
}

__global__ void k_scatter(const int4* __restrict__ esrc4,
                          const int4* __restrict__ edst4,
                          const float4* __restrict__ eval4,
                          int n_e4, int n_rows) {
    if (blockIdx.x == 0 && threadIdx.x < 2 * D) g_stats[threadIdx.x] = 0.f;
    int i = blockIdx.x * blockDim.x + threadIdx.x;
    if (i >= n_e4) return;
    int4 d = edst4[i];
    int4 s = esrc4[i];
    float4 v = eval4[i];
    scat1(d.x, s.x, v.x, n_rows);
    scat1(d.y, s.y, v.y, n_rows);
    scat1(d.z, s.z, v.z, n_rows);
    scat1(d.w, s.w, v.w, n_rows);
}

// ---------------------------------------------------------------------------
// K2: tensor-core GEMM y = x @ W (fp16 in, fp32 accum, fp16 out).
// Block: 128x128 tile, 8 warps as 4(m) x 2(n), warp tile 32x64.
// ---------------------------------------------------------------------------
#define SROW 136
#define GEMM_SMEM (2 * 128 * SROW * sizeof(__half))   // 69632 B

__global__ __launch_bounds__(256) void k_gemm_xw(const float* __restrict__ X,
                                                 const float* __restrict__ W,
                                                 int n_rows) {
    extern __shared__ __half smh[];
    __half* sA = smh;                 // [128][SROW]
    __half* sB = smh + 128 * SROW;    // [128][SROW]

    int tid = threadIdx.x;
    int wid = tid >> 5;
    int lane = tid & 31;
    int gr = lane >> 2;
    int tc = (lane & 3) * 2;

    int mbase = (wid & 3) * 32;
    int nbase = (wid >> 2) * 64;

#pragma unroll
    for (int q = 0; q < 16; q++) {
        int f = tid + 256 * q;
        int r = f >> 5;
        int kq = f & 31;
        int grow = blockIdx.x * 128 + r;
        float4 v = make_float4(0.f, 0.f, 0.f, 0.f);
        if (grow < n_rows)
            v = *reinterpret_cast<const float4*>(&X[(size_t)grow * D + kq * 4]);
        __half2 h0 = __floats2half2_rn(v.x, v.y);
        __half2 h1 = __floats2half2_rn(v.z, v.w);
        uint2 pk;
        pk.x = h2_as_u32(h0);
        pk.y = h2_as_u32(h1);
        *reinterpret_cast<uint2*>(&sA[r * SROW + kq * 4]) = pk;

        float4 w = *reinterpret_cast<const float4*>(&W[(size_t)r * D + kq * 4]);
        __half2 g0 = __floats2half2_rn(w.x, w.y);
        __half2 g1 = __floats2half2_rn(w.z, w.w);
        uint2 pw;
        pw.x = h2_as_u32(g0);
        pw.y = h2_as_u32(g1);
        *reinterpret_cast<uint2*>(&sB[r * SROW + kq * 4]) = pw;
    }
    __syncthreads();

    float c[2][8][4];
#pragma unroll
    for (int mt = 0; mt < 2; mt++)
#pragma unroll
        for (int nt = 0; nt < 8; nt++)
#pragma unroll
            for (int j = 0; j < 4; j++) c[mt][nt][j] = 0.f;

    const unsigned short* sBu = reinterpret_cast<const unsigned short*>(sB);

#pragma unroll
    for (int ks = 0; ks < 8; ks++) {
        int kb = ks * 16;
        unsigned int a[2][4];
#pragma unroll
        for (int mt = 0; mt < 2; mt++) {
            int r0 = mbase + mt * 16 + gr;
            a[mt][0] = *reinterpret_cast<const unsigned int*>(&sA[r0 * SROW + kb + tc]);
            a[mt][1] = *reinterpret_cast<const unsigned int*>(&sA[(r0 + 8) * SROW + kb + tc]);
            a[mt][2] = *reinterpret_cast<const unsigned int*>(&sA[r0 * SROW + kb + 8 + tc]);
            a[mt][3] = *reinterpret_cast<const unsigned int*>(&sA[(r0 + 8) * SROW + kb + 8 + tc]);
        }
#pragma unroll
        for (int nt = 0; nt < 8; nt++) {
            int nb = nbase + nt * 8 + gr;
            unsigned int b0 = (unsigned int)sBu[(kb + tc) * SROW + nb] |
                              ((unsigned int)sBu[(kb + tc + 1) * SROW + nb] << 16);
            unsigned int b1 = (unsigned int)sBu[(kb + 8 + tc) * SROW + nb] |
                              ((unsigned int)sBu[(kb + 8 + tc + 1) * SROW + nb] << 16);
#pragma unroll
            for (int mt = 0; mt < 2; mt++) {
                asm volatile(
                    "mma.sync.aligned.m16n8k16.row.col.f32.f16.f16.f32 "
                    "{%0,%1,%2,%3}, {%4,%5,%6,%7}, {%8,%9}, {%0,%1,%2,%3};\n"
                    : "+f"(c[mt][nt][0]), "+f"(c[mt][nt][1]),
                      "+f"(c[mt][nt][2]), "+f"(c[mt][nt][3])
                    : "r"(a[mt][0]), "r"(a[mt][1]), "r"(a[mt][2]), "r"(a[mt][3]),
                      "r"(b0), "r"(b1));
            }
        }
    }

    __half* Y = g_yh;
#pragma unroll
    for (int mt = 0; mt < 2; mt++) {
        int r0 = blockIdx.x * 128 + mbase + mt * 16 + gr;
#pragma unroll
        for (int nt = 0; nt < 8; nt++) {
            int cb = nbase + nt * 8 + tc;
            if (r0 < n_rows) {
                __half2 lo = __floats2half2_rn(c[mt][nt][0], c[mt][nt][1]);
                *reinterpret_cast<unsigned int*>(&Y[(size_t)r0 * D + cb]) = h2_as_u32(lo);
            }
            if (r0 + 8 < n_rows) {
                __half2 hi = __floats2half2_rn(c[mt][nt][2], c[mt][nt][3]);
                *reinterpret_cast<unsigned int*>(&Y[(size_t)(r0 + 8) * D + cb]) = h2_as_u32(hi);
            }
        }
    }
}

// ---------------------------------------------------------------------------
// K3: gather-reduce over fp16 y -> fp16 z rows, fused BN stats.
// Grid-stride warp-per-node; lane owns 4 columns. 6-edge unroll, int4 bucket
// loads, scalar FFMA accumulation (4 independent chains — R13-proven form).
// Resets g_cnt[node]=0 after reading (maintains all-zero invariant).
// ---------------------------------------------------------------------------
__device__ __forceinline__ void acc_edge(float4& acc, uint2 r, float v) {
    float2 a0 = __half22float2(u32_as_h2(r.x));
    float2 a1 = __half22float2(u32_as_h2(r.y));
    acc.x += a0.x * v;
    acc.y += a0.y * v;
    acc.z += a1.x * v;
    acc.w += a1.y * v;
}

__global__ __launch_bounds__(256, 7) void k_gather(int n_rows, int total_warps) {
    __shared__ float s_sum[D];
    __shared__ float s_sq[D];
    if (threadIdx.x < D) { s_sum[threadIdx.x] = 0.f; s_sq[threadIdx.x] = 0.f; }
    __syncthreads();

    int gwarp = (blockIdx.x * blockDim.x + threadIdx.x) >> 5;
    int lane = threadIdx.x & 31;
    const uint2* y2 = reinterpret_cast<const uint2*>(g_yh);
    uint2* z2 = reinterpret_cast<uint2*>(g_zh);

    float4 csum = make_float4(0.f, 0.f, 0.f, 0.f);
    float4 csq = make_float4(0.f, 0.f, 0.f, 0.f);

    for (int node = gwarp; node < n_rows; node += total_warps) {
        const int4* bucket4 = reinterpret_cast<const int4*>(&g_csr[(size_t)node << 6]);
        int deg = g_cnt[node];
        if (lane == 0) g_cnt[node] = 0;   // restore all-zero invariant
        if (deg > BUCKET) deg = BUCKET;

        float4 acc = make_float4(0.f, 0.f, 0.f, 0.f);
        int p = 0;
        for (; p + 5 < deg; p += 6) {          // 6 edges = 3 int4 loads
            int4 e4[3];
#pragma unroll
            for (int q = 0; q < 3; q++) e4[q] = bucket4[(p >> 1) + q];
            uint2 r[6];
#pragma unroll
            for (int q = 0; q < 3; q++) {
                r[2 * q]     = y2[(size_t)e4[q].x * 32 + lane];
                r[2 * q + 1] = y2[(size_t)e4[q].z * 32 + lane];
            }
#pragma unroll
            for (int q = 0; q < 3; q++) {
                acc_edge(acc, r[2 * q],     __int_as_float(e4[q].y));
                acc_edge(acc, r[2 * q + 1], __int_as_float(e4[q].w));
            }
        }
        for (; p + 1 < deg; p += 2) {
            int4 e = bucket4[p >> 1];
            uint2 r0 = y2[(size_t)e.x * 32 + lane];
            uint2 r1 = y2[(size_t)e.z * 32 + lane];
            acc_edge(acc, r0, __int_as_float(e.y));
            acc_edge(acc, r1, __int_as_float(e.w));
        }
        if (p < deg) {
            int2 e0 = g_csr[((size_t)node << 6) + p];
            uint2 ra = y2[(size_t)e0.x * 32 + lane];
            acc_edge(acc, ra, __int_as_float(e0.y));
        }

        __half2 z01 = __floats2half2_rn(acc.x, acc.y);
        __half2 z23 = __floats2half2_rn(acc.z, acc.w);
        uint2 zo;
        zo.x = h2_as_u32(z01);
        zo.y = h2_as_u32(z23);
        z2[(size_t)node * 32 + lane] = zo;

        float2 f01 = __half22float2(z01);
        float2 f23 = __half22float2(z23);
        csum.x += f01.x; csum.y += f01.y; csum.z += f23.x; csum.w += f23.y;
        csq.x += f01.x * f01.x; csq.y += f01.y * f01.y;
        csq.z += f23.x * f23.x; csq.w += f23.y * f23.y;
    }

    int c0 = lane * 4;
    atomicAdd(&s_sum[c0 + 0], csum.x);
    atomicAdd(&s_sum[c0 + 1], csum.y);
    atomicAdd(&s_sum[c0 + 2], csum.z);
    atomicAdd(&s_sum[c0 + 3], csum.w);
    atomicAdd(&s_sq[c0 + 0], csq.x);
    atomicAdd(&s_sq[c0 + 1], csq.y);
    atomicAdd(&s_sq[c0 + 2], csq.z);
    atomicAdd(&s_sq[c0 + 3], csq.w);
    __syncthreads();
    if (threadIdx.x < D) {
        atomicAdd(&g_stats[threadIdx.x], s_sum[threadIdx.x]);
        atomicAdd(&g_stats[D + threadIdx.x], s_sq[threadIdx.x]);
    }
}

// ---------------------------------------------------------------------------
// K4: normalize fp16 z -> fp32 out. Bias cancels in BN.
// ---------------------------------------------------------------------------
__global__ __launch_bounds__(256) void k_norm(float4* __restrict__ out,
                                              const float* __restrict__ gamma,
                                              const float* __restrict__ beta,
                                              float inv_n, int n_rows) {
    __shared__ float s_scale[D];
    __shared__ float s_shift[D];
    if (threadIdx.x < D) {
        int c = threadIdx.x;
        float mean = g_stats[c] * inv_n;
        float var = g_stats[D + c] * inv_n - mean * mean;
        float inv = rsqrtf(var + BN_EPS);
        float sc = gamma[c] * inv;
        s_scale[c] = sc;
        s_shift[c] = beta[c] - mean * sc;
    }
    __syncthreads();

    const uint2* z2 = reinterpret_cast<const uint2*>(g_zh);
    size_t total = (size_t)n_rows * (D / 4);
    size_t stride = (size_t)gridDim.x * blockDim.x;
    for (size_t i = (size_t)blockIdx.x * blockDim.x + threadIdx.x; i < total;
         i += stride) {
        int c4 = (int)(i & 31);
        uint2 zr = z2[i];
        float2 f01 = __half22float2(u32_as_h2(zr.x));
        float2 f23 = __half22float2(u32_as_h2(zr.y));
        float4 sc = reinterpret_cast<const float4*>(s_scale)[c4];
        float4 sh = reinterpret_cast<const float4*>(s_shift)[c4];
        float4 v;
        v.x = f01.x * sc.x + sh.x;
        v.y = f01.y * sc.y + sh.y;
        v.z = f23.x * sc.z + sh.z;
        v.w = f23.y * sc.w + sh.w;
        out[i] = v;
    }
}

// ---------------------------------------------------------------------------
extern "C" void kernel_launch(void* const* d_in, const int* in_sizes, int n_in,
                              void* d_out, int out_size) {
    const float* x    = (const float*)d_in[0];
    const int*   esrc = (const int*)d_in[1];
    const int*   edst = (const int*)d_in[2];
    const float* eval = (const float*)d_in[3];
    const float* W    = (const float*)d_in[4];
    // d_in[5] = bias: cancels analytically in BatchNorm — unused.
    const float* gamm = (const float*)d_in[6];
    const float* beta = (const float*)d_in[7];
    float* out = (float*)d_out;

    int n_rows = in_sizes[0] / D;      // 100000
    int n_edges = in_sizes[1];         // 1600000

    static cudaStream_t s2 = nullptr;
    static cudaEvent_t ev_fork = nullptr, ev_join = nullptr;
    if (s2 == nullptr) {
        cudaFuncSetAttribute(k_gemm_xw, cudaFuncAttributeMaxDynamicSharedMemorySize,
                             (int)GEMM_SMEM);
        cudaStreamCreateWithFlags(&s2, cudaStreamNonBlocking);
        cudaEventCreateWithFlags(&ev_fork, cudaEventDisableTiming);
        cudaEventCreateWithFlags(&ev_join, cudaEventDisableTiming);
    }

    // Fork: tensor-core GEMM on s2, concurrent with bucket-CSR scatter.
    cudaEventRecord(ev_fork, 0);
    cudaStreamWaitEvent(s2, ev_fork, 0);
    k_gemm_xw<<<(n_rows + 127) / 128, 256, GEMM_SMEM, s2>>>(x, W, n_rows);
    cudaEventRecord(ev_join, s2);

    // Bucket scatter on default stream. g_cnt is all-zero at entry
    // (static init on call 1; gather resets it every call). Block 0 zeros stats.
    k_scatter<<<(n_edges / 4 + 255) / 256, 256>>>((const int4*)esrc,
                                                  (const int4*)edst,
                                                  (const float4*)eval,
                                                  n_edges / 4, n_rows);

    // Join: gather needs both y and CSR.
    cudaStreamWaitEvent(0, ev_join, 0);

    {
        int blocks = 1036;               // 7 blocks/SM, one wave
        int total_warps = blocks * (256 / 32);
        k_gather<<<blocks, 256>>>(n_rows, total_warps);
    }
    k_norm<<<1776, 256>>>((float4*)out, gamm, beta, 1.0f / (float)n_rows, n_rows);
}

// round 16
// speedup vs baseline: 1.9305x; 1.8863x over previous
#include <cuda_runtime.h>
#include <cuda_fp16.h>

#define N_NODES 100000
#define E_EDGES 1600000
#define D 128
#define BN_EPS 1e-5f
#define MAX_N 131072
#define BUCKET 64          // padded CSR capacity per node; P(deg>=64)~1e-18

// Scratch (static device globals — allocation-free).
__device__ __half g_yh[(size_t)N_NODES * D];   // 25.6 MB: y = x @ W (fp16)
__device__ __half g_zh[(size_t)N_NODES * D];   // 25.6 MB: z = A @ y (fp16)
__device__ int    g_cnt[MAX_N];                // per-dst cursor/degree
__device__ int2   g_csr[(size_t)MAX_N * BUCKET];  // 67 MB padded buckets
__device__ float  g_stats[2 * D];

// ---------------- bit-reinterpret helpers ----------------
__device__ __forceinline__ unsigned int h2_as_u32(__half2 h) {
    return *reinterpret_cast<unsigned int*>(&h);
}
__device__ __forceinline__ __half2 u32_as_h2(unsigned int u) {
    return *reinterpret_cast<__half2*>(&u);
}

// ---------------------------------------------------------------------------
// K0: zero counters + stats (R13-proven structure — do not fold away)
// ---------------------------------------------------------------------------
__global__ void k_zero_small(int n_rows) {
    int i = blockIdx.x * blockDim.x + threadIdx.x;
    if (i < n_rows) g_cnt[i] = 0;
    if (blockIdx.x == 0 && threadIdx.x < 2 * D) g_stats[threadIdx.x] = 0.f;
}

// ---------------------------------------------------------------------------
// K1: scatter edges into padded buckets (4 edges per thread, int4 loads)
// ---------------------------------------------------------------------------
__device__ __forceinline__ void scat1(int d, int s, float v, int n_rows) {
    if ((unsigned)d < (unsigned)n_rows) {
        int slot = atomicAdd(&g_cnt[d], 1);
        if (slot < BUCKET) {
            int ss = ((unsigned)s < (unsigned)n_rows) ? s : 0;
            g_csr[((size_t)d << 6) + slot] = make_int2(ss, __float_as_int(v));
        }
    }
}

__global__ void k_scatter(const int4* __restrict__ esrc4,
                          const int4* __restrict__ edst4,
                          const float4* __restrict__ eval4,
                          int n_e4, int n_rows) {
    int i = blockIdx.x * blockDim.x + threadIdx.x;
    if (i >= n_e4) return;
    int4 d = edst4[i];
    int4 s = esrc4[i];
    float4 v = eval4[i];
    scat1(d.x, s.x, v.x, n_rows);
    scat1(d.y, s.y, v.y, n_rows);
    scat1(d.z, s.z, v.z, n_rows);
    scat1(d.w, s.w, v.w, n_rows);
}

// ---------------------------------------------------------------------------
// K2: tensor-core GEMM y = x @ W (fp16 in, fp32 accum, fp16 out).
// Block: 128x128 tile, 8 warps as 4(m) x 2(n), warp tile 32x64.
// ---------------------------------------------------------------------------
#define SROW 136
#define GEMM_SMEM (2 * 128 * SROW * sizeof(__half))   // 69632 B

__global__ __launch_bounds__(256) void k_gemm_xw(const float* __restrict__ X,
                                                 const float* __restrict__ W,
                                                 int n_rows) {
    extern __shared__ __half smh[];
    __half* sA = smh;                 // [128][SROW]
    __half* sB = smh + 128 * SROW;    // [128][SROW]

    int tid = threadIdx.x;
    int wid = tid >> 5;
    int lane = tid & 31;
    int gr = lane >> 2;
    int tc = (lane & 3) * 2;

    int mbase = (wid & 3) * 32;
    int nbase = (wid >> 2) * 64;

#pragma unroll
    for (int q = 0; q < 16; q++) {
        int f = tid + 256 * q;
        int r = f >> 5;
        int kq = f & 31;
        int grow = blockIdx.x * 128 + r;
        float4 v = make_float4(0.f, 0.f, 0.f, 0.f);
        if (grow < n_rows)
            v = *reinterpret_cast<const float4*>(&X[(size_t)grow * D + kq * 4]);
        __half2 h0 = __floats2half2_rn(v.x, v.y);
        __half2 h1 = __floats2half2_rn(v.z, v.w);
        uint2 pk;
        pk.x = h2_as_u32(h0);
        pk.y = h2_as_u32(h1);
        *reinterpret_cast<uint2*>(&sA[r * SROW + kq * 4]) = pk;

        float4 w = *reinterpret_cast<const float4*>(&W[(size_t)r * D + kq * 4]);
        __half2 g0 = __floats2half2_rn(w.x, w.y);
        __half2 g1 = __floats2half2_rn(w.z, w.w);
        uint2 pw;
        pw.x = h2_as_u32(g0);
        pw.y = h2_as_u32(g1);
        *reinterpret_cast<uint2*>(&sB[r * SROW + kq * 4]) = pw;
    }
    __syncthreads();

    float c[2][8][4];
#pragma unroll
    for (int mt = 0; mt < 2; mt++)
#pragma unroll
        for (int nt = 0; nt < 8; nt++)
#pragma unroll
            for (int j = 0; j < 4; j++) c[mt][nt][j] = 0.f;

    const unsigned short* sBu = reinterpret_cast<const unsigned short*>(sB);

#pragma unroll
    for (int ks = 0; ks < 8; ks++) {
        int kb = ks * 16;
        unsigned int a[2][4];
#pragma unroll
        for (int mt = 0; mt < 2; mt++) {
            int r0 = mbase + mt * 16 + gr;
            a[mt][0] = *reinterpret_cast<const unsigned int*>(&sA[r0 * SROW + kb + tc]);
            a[mt][1] = *reinterpret_cast<const unsigned int*>(&sA[(r0 + 8) * SROW + kb + tc]);
            a[mt][2] = *reinterpret_cast<const unsigned int*>(&sA[r0 * SROW + kb + 8 + tc]);
            a[mt][3] = *reinterpret_cast<const unsigned int*>(&sA[(r0 + 8) * SROW + kb + 8 + tc]);
        }
#pragma unroll
        for (int nt = 0; nt < 8; nt++) {
            int nb = nbase + nt * 8 + gr;
            unsigned int b0 = (unsigned int)sBu[(kb + tc) * SROW + nb] |
                              ((unsigned int)sBu[(kb + tc + 1) * SROW + nb] << 16);
            unsigned int b1 = (unsigned int)sBu[(kb + 8 + tc) * SROW + nb] |
                              ((unsigned int)sBu[(kb + 8 + tc + 1) * SROW + nb] << 16);
#pragma unroll
            for (int mt = 0; mt < 2; mt++) {
                asm volatile(
                    "mma.sync.aligned.m16n8k16.row.col.f32.f16.f16.f32 "
                    "{%0,%1,%2,%3}, {%4,%5,%6,%7}, {%8,%9}, {%0,%1,%2,%3};\n"
                    : "+f"(c[mt][nt][0]), "+f"(c[mt][nt][1]),
                      "+f"(c[mt][nt][2]), "+f"(c[mt][nt][3])
                    : "r"(a[mt][0]), "r"(a[mt][1]), "r"(a[mt][2]), "r"(a[mt][3]),
                      "r"(b0), "r"(b1));
            }
        }
    }

    __half* Y = g_yh;
#pragma unroll
    for (int mt = 0; mt < 2; mt++) {
        int r0 = blockIdx.x * 128 + mbase + mt * 16 + gr;
#pragma unroll
        for (int nt = 0; nt < 8; nt++) {
            int cb = nbase + nt * 8 + tc;
            if (r0 < n_rows) {
                __half2 lo = __floats2half2_rn(c[mt][nt][0], c[mt][nt][1]);
                *reinterpret_cast<unsigned int*>(&Y[(size_t)r0 * D + cb]) = h2_as_u32(lo);
            }
            if (r0 + 8 < n_rows) {
                __half2 hi = __floats2half2_rn(c[mt][nt][2], c[mt][nt][3]);
                *reinterpret_cast<unsigned int*>(&Y[(size_t)(r0 + 8) * D + cb]) = h2_as_u32(hi);
            }
        }
    }
}

// ---------------------------------------------------------------------------
// K3: gather-reduce over fp16 y -> fp16 z rows, fused BN stats.
// Grid-stride warp-per-node; lane owns 4 columns. 6-edge unroll, int4 bucket
// loads, scalar FFMA accumulation. EXACT R13 form (no g_cnt writes).
// ---------------------------------------------------------------------------
__device__ __forceinline__ void acc_edge(float4& acc, uint2 r, float v) {
    float2 a0 = __half22float2(u32_as_h2(r.x));
    float2 a1 = __half22float2(u32_as_h2(r.y));
    acc.x += a0.x * v;
    acc.y += a0.y * v;
    acc.z += a1.x * v;
    acc.w += a1.y * v;
}

__global__ __launch_bounds__(256, 7) void k_gather(int n_rows, int total_warps) {
    __shared__ float s_sum[D];
    __shared__ float s_sq[D];
    if (threadIdx.x < D) { s_sum[threadIdx.x] = 0.f; s_sq[threadIdx.x] = 0.f; }
    __syncthreads();

    int gwarp = (blockIdx.x * blockDim.x + threadIdx.x) >> 5;
    int lane = threadIdx.x & 31;
    const uint2* y2 = reinterpret_cast<const uint2*>(g_yh);
    uint2* z2 = reinterpret_cast<uint2*>(g_zh);

    float4 csum = make_float4(0.f, 0.f, 0.f, 0.f);
    float4 csq = make_float4(0.f, 0.f, 0.f, 0.f);

    for (int node = gwarp; node < n_rows; node += total_warps) {
        const int4* bucket4 = reinterpret_cast<const int4*>(&g_csr[(size_t)node << 6]);
        int deg = g_cnt[node];
        if (deg > BUCKET) deg = BUCKET;

        float4 acc = make_float4(0.f, 0.f, 0.f, 0.f);
        int p = 0;
        for (; p + 5 < deg; p += 6) {          // 6 edges = 3 int4 loads
            int4 e4[3];
#pragma unroll
            for (int q = 0; q < 3; q++) e4[q] = bucket4[(p >> 1) + q];
            uint2 r[6];
#pragma unroll
            for (int q = 0; q < 3; q++) {
                r[2 * q]     = y2[(size_t)e4[q].x * 32 + lane];
                r[2 * q + 1] = y2[(size_t)e4[q].z * 32 + lane];
            }
#pragma unroll
            for (int q = 0; q < 3; q++) {
                acc_edge(acc, r[2 * q],     __int_as_float(e4[q].y));
                acc_edge(acc, r[2 * q + 1], __int_as_float(e4[q].w));
            }
        }
        for (; p + 1 < deg; p += 2) {
            int4 e = bucket4[p >> 1];
            uint2 r0 = y2[(size_t)e.x * 32 + lane];
            uint2 r1 = y2[(size_t)e.z * 32 + lane];
            acc_edge(acc, r0, __int_as_float(e.y));
            acc_edge(acc, r1, __int_as_float(e.w));
        }
        if (p < deg) {
            int2 e0 = g_csr[((size_t)node << 6) + p];
            uint2 ra = y2[(size_t)e0.x * 32 + lane];
            acc_edge(acc, ra, __int_as_float(e0.y));
        }

        __half2 z01 = __floats2half2_rn(acc.x, acc.y);
        __half2 z23 = __floats2half2_rn(acc.z, acc.w);
        uint2 zo;
        zo.x = h2_as_u32(z01);
        zo.y = h2_as_u32(z23);
        z2[(size_t)node * 32 + lane] = zo;

        float2 f01 = __half22float2(z01);
        float2 f23 = __half22float2(z23);
        csum.x += f01.x; csum.y += f01.y; csum.z += f23.x; csum.w += f23.y;
        csq.x += f01.x * f01.x; csq.y += f01.y * f01.y;
        csq.z += f23.x * f23.x; csq.w += f23.y * f23.y;
    }

    int c0 = lane * 4;
    atomicAdd(&s_sum[c0 + 0], csum.x);
    atomicAdd(&s_sum[c0 + 1], csum.y);
    atomicAdd(&s_sum[c0 + 2], csum.z);
    atomicAdd(&s_sum[c0 + 3], csum.w);
    atomicAdd(&s_sq[c0 + 0], csq.x);
    atomicAdd(&s_sq[c0 + 1], csq.y);
    atomicAdd(&s_sq[c0 + 2], csq.z);
    atomicAdd(&s_sq[c0 + 3], csq.w);
    __syncthreads();
    if (threadIdx.x < D) {
        atomicAdd(&g_stats[threadIdx.x], s_sum[threadIdx.x]);
        atomicAdd(&g_stats[D + threadIdx.x], s_sq[threadIdx.x]);
    }
}

// ---------------------------------------------------------------------------
// K4: normalize fp16 z -> fp32 out. Bias cancels in BN.
// Vectorized: 8 columns per thread (uint4 z read, 2x float4 out writes).
// ---------------------------------------------------------------------------
__global__ __launch_bounds__(256) void k_norm(float4* __restrict__ out,
                                              const float* __restrict__ gamma,
                                              const float* __restrict__ beta,
                                              float inv_n, int n_rows) {
    __shared__ float s_scale[D];
    __shared__ float s_shift[D];
    if (threadIdx.x < D) {
        int c = threadIdx.x;
        float mean = g_stats[c] * inv_n;
        float var = g_stats[D + c] * inv_n - mean * mean;
        float inv = rsqrtf(var + BN_EPS);
        float sc = gamma[c] * inv;
        s_scale[c] = sc;
        s_shift[c] = beta[c] - mean * sc;
    }
    __syncthreads();

    const uint4* z4 = reinterpret_cast<const uint4*>(g_zh);   // 16 uint4 per row
    size_t total = (size_t)n_rows * (D / 8);
    size_t stride = (size_t)gridDim.x * blockDim.x;
    for (size_t i = (size_t)blockIdx.x * blockDim.x + threadIdx.x; i < total;
         i += stride) {
        int c8 = (int)(i & 15);             // which 8-col group
        uint4 zr = z4[i];
        float2 f0 = __half22float2(u32_as_h2(zr.x));
        float2 f1 = __half22float2(u32_as_h2(zr.y));
        float2 f2 = __half22float2(u32_as_h2(zr.z));
        float2 f3 = __half22float2(u32_as_h2(zr.w));
        float4 sc0 = reinterpret_cast<const float4*>(s_scale)[c8 * 2];
        float4 sc1 = reinterpret_cast<const float4*>(s_scale)[c8 * 2 + 1];
        float4 sh0 = reinterpret_cast<const float4*>(s_shift)[c8 * 2];
        float4 sh1 = reinterpret_cast<const float4*>(s_shift)[c8 * 2 + 1];
        float4 v0, v1;
        v0.x = f0.x * sc0.x + sh0.x;
        v0.y = f0.y * sc0.y + sh0.y;
        v0.z = f1.x * sc0.z + sh0.z;
        v0.w = f1.y * sc0.w + sh0.w;
        v1.x = f2.x * sc1.x + sh1.x;
        v1.y = f2.y * sc1.y + sh1.y;
        v1.z = f3.x * sc1.z + sh1.z;
        v1.w = f3.y * sc1.w + sh1.w;
        out[i * 2]     = v0;
        out[i * 2 + 1] = v1;
    }
}

// ---------------------------------------------------------------------------
extern "C" void kernel_launch(void* const* d_in, const int* in_sizes, int n_in,
                              void* d_out, int out_size) {
    const float* x    = (const float*)d_in[0];
    const int*   esrc = (const int*)d_in[1];
    const int*   edst = (const int*)d_in[2];
    const float* eval = (const float*)d_in[3];
    const float* W    = (const float*)d_in[4];
    // d_in[5] = bias: cancels analytically in BatchNorm — unused.
    const float* gamm = (const float*)d_in[6];
    const float* beta = (const float*)d_in[7];
    float* out = (float*)d_out;

    int n_rows = in_sizes[0] / D;      // 100000
    int n_edges = in_sizes[1];         // 1600000
    int nb = (n_rows + 255) / 256;

    static cudaStream_t s2 = nullptr;
    static cudaEvent_t ev_fork = nullptr, ev_join = nullptr;
    if (s2 == nullptr) {
        cudaFuncSetAttribute(k_gemm_xw, cudaFuncAttributeMaxDynamicSharedMemorySize,
                             (int)GEMM_SMEM);
        cudaStreamCreateWithFlags(&s2, cudaStreamNonBlocking);
        cudaEventCreateWithFlags(&ev_fork, cudaEventDisableTiming);
        cudaEventCreateWithFlags(&ev_join, cudaEventDisableTiming);
    }

    // Fork: tensor-core GEMM on s2, concurrent with bucket-CSR build.
    cudaEventRecord(ev_fork, 0);
    cudaStreamWaitEvent(s2, ev_fork, 0);
    k_gemm_xw<<<(n_rows + 127) / 128, 256, GEMM_SMEM, s2>>>(x, W, n_rows);
    cudaEventRecord(ev_join, s2);

    // Bucket CSR build on default stream (R13-proven: explicit zero kernel).
    k_zero_small<<<nb, 256>>>(n_rows);
    k_scatter<<<(n_edges / 4 + 255) / 256, 256>>>((const int4*)esrc,
                                                  (const int4*)edst,
                                                  (const float4*)eval,
                                                  n_edges / 4, n_rows);

    // Join: gather needs both y and CSR.
    cudaStreamWaitEvent(0, ev_join, 0);

    {
        int blocks = 1036;               // 7 blocks/SM, one wave
        int total_warps = blocks * (256 / 32);
        k_gather<<<blocks, 256>>>(n_rows, total_warps);
    }
    k_norm<<<1776, 256>>>((float4*)out, gamm, beta, 1.0f / (float)n_rows, n_rows);
}